// round 1
// baseline (speedup 1.0000x reference)
#include <cuda_runtime.h>

// DeepFilterNet DF coef op, GB300.
// spec  : [B=32, 1, T=1000, F=481, 2] f32
// coefs : [B, T, ORDER=5, 96, 2] f32
// alpha : [B, T, 1] f32
// out   : same shape as spec; first 96 freq bins blended with 5-tap complex FIR.
//
// Memory-bound: ~370 MB total traffic. One thread per complex (float2) element,
// fully coalesced; L2 absorbs the 5x temporal reuse of the lower-96-bin rows.

#define B_DIM 32
#define T_DIM 1000
#define F_DIM 481
#define F_DF 96
#define ORDER 5
#define LOOKAHEAD 2

__global__ void __launch_bounds__(256) df_coef_kernel(
    const float2* __restrict__ spec,
    const float2* __restrict__ coefs,
    const float*  __restrict__ alpha,
    float2* __restrict__ out,
    int total)   // B*T*F complex elements
{
    int e = blockIdx.x * blockDim.x + threadIdx.x;
    if (e >= total) return;

    int bt = e / F_DIM;          // frame index b*T + t
    int f  = e - bt * F_DIM;     // freq bin

    float2 s = spec[e];          // always needed (copy or blend base)

    if (f >= F_DF) {             // upper 385 bins: passthrough
        out[e] = s;
        return;
    }

    int t = bt % T_DIM;

    // coefs layout: [(bt*5 + i)*96 + f] float2
    const float2* cptr = coefs + (size_t)bt * (ORDER * F_DF) + f;

    float re = 0.0f, im = 0.0f;
    #pragma unroll
    for (int i = 0; i < ORDER; i++) {
        int tt = t + i - (ORDER - LOOKAHEAD - 1);   // t + i - 2
        float2 w = make_float2(0.0f, 0.0f);
        if (tt >= 0 && tt < T_DIM) {
            // same b, time tt, bin f: index (bt + i - 2)*481 + f
            w = spec[(size_t)(bt + i - (ORDER - LOOKAHEAD - 1)) * F_DIM + f];
        }
        float2 c = cptr[(size_t)i * F_DF];
        re = fmaf(w.x, c.x, re);
        re = fmaf(-w.y, c.y, re);
        im = fmaf(w.y, c.x, im);
        im = fmaf(w.x, c.y, im);
    }

    float a  = alpha[bt];
    float na = 1.0f - a;
    out[e] = make_float2(fmaf(re, a, s.x * na), fmaf(im, a, s.y * na));
}

extern "C" void kernel_launch(void* const* d_in, const int* in_sizes, int n_in,
                              void* d_out, int out_size)
{
    const float2* spec  = (const float2*)d_in[0];
    const float2* coefs = (const float2*)d_in[1];
    const float*  alpha = (const float*)d_in[2];
    float2* out = (float2*)d_out;

    const int total = B_DIM * T_DIM * F_DIM;   // 15,392,000 complex elements
    const int threads = 256;
    const int blocks = (total + threads - 1) / threads;
    df_coef_kernel<<<blocks, threads>>>(spec, coefs, alpha, out, total);
}

// round 2
// speedup vs baseline: 1.0956x; 1.0956x over previous
#include <cuda_runtime.h>

// DeepFilterNet DF coef op, GB300 — R2: float4-vectorized flat kernel.
// spec  : [B=32, 1, T=1000, F=481, 2] f32
// coefs : [B, T, 5, 96, 2] f32
// alpha : [B, T, 1] f32
// out   : same as spec; first 96 bins = 5-tap complex FIR blended with alpha.
//
// Flat pairing: thread p handles complex elements e0=2p, e0+1. Since the
// total element count is even and buffers are 256B-aligned, float4 loads of
// spec/out are always aligned (row stride 481 is odd, but pairing is flat).
// ~80% of pairs are pure upper-bin passthrough: one LDG.128 + STG.128.

#define B_DIM 32
#define T_DIM 1000
#define F_DIM 481
#define F_DF 96
#define ORDER 5

#define NPAIRS ((B_DIM * T_DIM * F_DIM) / 2)   // 7,696,000

__device__ __forceinline__ float2 df_elem(
    const float2* __restrict__ spec,
    const float2* __restrict__ coefs,
    const float*  __restrict__ alpha,
    int bt, int f, float2 s)
{
    int t = bt % T_DIM;
    const float2* cptr = coefs + (size_t)bt * (ORDER * F_DF) + f;

    float re = 0.0f, im = 0.0f;
    #pragma unroll
    for (int i = 0; i < ORDER; i++) {
        int tt = t + i - 2;                       // ORDER - LOOKAHEAD - 1 = 2
        float2 w = make_float2(0.0f, 0.0f);
        if (tt >= 0 && tt < T_DIM)
            w = spec[(size_t)(bt + i - 2) * F_DIM + f];
        float2 c = cptr[(size_t)i * F_DF];
        re = fmaf(w.x, c.x, re);
        re = fmaf(-w.y, c.y, re);
        im = fmaf(w.y, c.x, im);
        im = fmaf(w.x, c.y, im);
    }

    float a  = alpha[bt];
    float na = 1.0f - a;
    return make_float2(fmaf(re, a, s.x * na), fmaf(im, a, s.y * na));
}

__global__ void __launch_bounds__(256) df_coef_kernel(
    const float4* __restrict__ spec4,
    const float2* __restrict__ spec2,
    const float2* __restrict__ coefs,
    const float*  __restrict__ alpha,
    float4* __restrict__ out4,
    float2* __restrict__ out2)
{
    int p = blockIdx.x * blockDim.x + threadIdx.x;
    if (p >= NPAIRS) return;

    int e0 = 2 * p;
    int bt = e0 / F_DIM;
    int f0 = e0 - bt * F_DIM;

    // Fast path: both elements in passthrough region (f0 and f0+1 in [96,480]).
    if (f0 >= F_DF && f0 < F_DIM - 1) {
        float4 s4 = __ldcs(&spec4[p]);     // stream-once, don't pollute L2
        __stcs(&out4[p], s4);
        return;
    }

    float4 s4 = spec4[p];                  // DF region: cacheable (tap reuse)
    float2 s0 = make_float2(s4.x, s4.y);
    float2 s1 = make_float2(s4.z, s4.w);

    // element 0
    float2 r0 = (f0 < F_DF) ? df_elem(spec2, coefs, alpha, bt, f0, s0) : s0;

    // element 1: same row unless f0 == 480 (then it's f=0 of row bt+1)
    int bt1 = bt, f1 = f0 + 1;
    if (f0 == F_DIM - 1) { bt1 = bt + 1; f1 = 0; }
    float2 r1 = (f1 < F_DF) ? df_elem(spec2, coefs, alpha, bt1, f1, s1) : s1;

    __stcs(&out4[p], make_float4(r0.x, r0.y, r1.x, r1.y));
}

extern "C" void kernel_launch(void* const* d_in, const int* in_sizes, int n_in,
                              void* d_out, int out_size)
{
    const float4* spec4 = (const float4*)d_in[0];
    const float2* spec2 = (const float2*)d_in[0];
    const float2* coefs = (const float2*)d_in[1];
    const float*  alpha = (const float*)d_in[2];

    const int threads = 256;
    const int blocks = (NPAIRS + threads - 1) / threads;
    df_coef_kernel<<<blocks, threads>>>(spec4, spec2, coefs, alpha,
                                        (float4*)d_out, (float2*)d_out);
}